// round 17
// baseline (speedup 1.0000x reference)
#include <cuda_runtime.h>
#include <cuda_bf16.h>
#include <cstdint>

#define NN   4096
#define FIN  512
#define HH   8
#define FO   64
#define LALPHA 0.2f
#define NW   128        // mask words per row
#define JTT  64         // j per tile
#define NJT  (NN/JTT)   // 64 tiles
#define NTF  8          // n-tiles of 8 (64 feats; Z now scalar)
#define GT_U4 2048      // uint4 per (h,jt) G tile block = 32768 B
#define ROWS 256        // i-rows per CTA (32 per warp, 2 row-fragments)
#define PAD  132

typedef unsigned long long u64;

// ---------------- f32x2 helpers (k_wh) ----------------
__device__ __forceinline__ u64 pk2(float lo, float hi) {
    u64 r; asm("mov.b64 %0, {%1,%2};" : "=l"(r) : "f"(lo), "f"(hi)); return r;
}
__device__ __forceinline__ void fma2(u64 &d, u64 a, u64 b) {
    asm("fma.rn.f32x2 %0, %1, %2, %3;" : "=l"(d) : "l"(a), "l"(b), "l"(d));
}
__device__ __forceinline__ void upk2(float &lo, float &hi, u64 v) {
    asm("mov.b64 {%0,%1}, %2;" : "=f"(lo), "=f"(hi) : "l"(v));
}

// ---------------- mma / cp.async helpers (arch-neutral PTX) ----------------
__device__ __forceinline__ uint32_t smem_u32(const void* p) {
    uint32_t a;
    asm("{ .reg .u64 t; cvta.to.shared.u64 t, %1; cvt.u32.u64 %0, t; }" : "=r"(a) : "l"(p));
    return a;
}
__device__ __forceinline__ void mma16816(float* c, const uint32_t* a, uint32_t b0, uint32_t b1) {
    asm volatile("mma.sync.aligned.m16n8k16.row.col.f32.bf16.bf16.f32 "
        "{%0,%1,%2,%3}, {%4,%5,%6,%7}, {%8,%9}, {%0,%1,%2,%3};"
        : "+f"(c[0]), "+f"(c[1]), "+f"(c[2]), "+f"(c[3])
        : "r"(a[0]), "r"(a[1]), "r"(a[2]), "r"(a[3]), "r"(b0), "r"(b1));
}
__device__ __forceinline__ void cpa16(uint32_t d, const void* s) {
    asm volatile("cp.async.cg.shared.global [%0], [%1], 16;" :: "r"(d), "l"(s));
}
__device__ __forceinline__ void cpa4(uint32_t d, const void* s) {
    asm volatile("cp.async.ca.shared.global [%0], [%1], 4;" :: "r"(d), "l"(s));
}
#define CP_COMMIT() asm volatile("cp.async.commit_group;" ::: "memory")
#define CP_WAIT0()  asm volatile("cp.async.wait_group 0;" ::: "memory")

// ---------------- scratch ----------------
__device__ float    g_Wh[(size_t)HH*NN*FO];
__device__ unsigned g_bits[(size_t)NN*NW];
__device__ float    g_s [HH*NN], g_E1[HH*NN], g_E2[HH*NN];
__device__ float    g_dd[HH*NN], g_F1[HH*NN], g_F2[HH*NN];
__device__ uint4    g_G[(size_t)HH*NJT*GT_U4];   // pre-fragmented split-bf16 G, 16.8 MB

// ---------------- K1: bit-pack adjacency ----------------
__global__ void k_bitpack(const int* __restrict__ adj) {
    int t = blockIdx.x * blockDim.x + threadIdx.x;
    int w = t >> 5, lane = t & 31;
    int v = adj[(size_t)w * 32 + lane];
    unsigned b = __ballot_sync(0xffffffffu, v > 0);
    if (lane == 0) g_bits[w] = b;
}

// ---------------- K2: Wh[h] = X @ W[h] (f32x2) ----------------
__global__ __launch_bounds__(256, 2) void k_wh(const float* __restrict__ X,
                                               const float* __restrict__ W) {
    __shared__ float As[32][PAD];
    __shared__ float Bs[32][64];
    const int h = blockIdx.y, i0 = blockIdx.x * 128, tid = threadIdx.x;
    const int tx = tid & 15, ty = tid >> 4;
    const float* Wb = W + (size_t)h * FIN * FO;
    u64 acc[4][4] = {};
    for (int kt = 0; kt < FIN; kt += 32) {
        __syncthreads();
        {
            int k4 = tid & 7, il = tid >> 3;
            #pragma unroll
            for (int rep = 0; rep < 4; rep++) {
                int i = il + rep * 32;
                float4 f = *(const float4*)&X[(size_t)(i0 + i) * FIN + kt + k4 * 4];
                As[k4*4+0][i] = f.x; As[k4*4+1][i] = f.y;
                As[k4*4+2][i] = f.z; As[k4*4+3][i] = f.w;
            }
        }
        {
            int f4 = tid & 15, k = tid >> 4;
            #pragma unroll
            for (int rep = 0; rep < 2; rep++) {
                int kk = k + rep * 16;
                *(float4*)&Bs[kk][f4*4] = *(const float4*)&Wb[(size_t)(kt+kk)*FO + f4*4];
            }
        }
        __syncthreads();
        #pragma unroll
        for (int k = 0; k < 32; k++) {
            float4 pa = *(const float4*)&As[k][ty*8];
            float4 pb = *(const float4*)&As[k][ty*8 + 4];
            u64 p[4] = { pk2(pa.x, pa.y), pk2(pa.z, pa.w),
                         pk2(pb.x, pb.y), pk2(pb.z, pb.w) };
            float4 vv = *(const float4*)&Bs[k][tx*4];
            u64 v0 = pk2(vv.x, vv.x), v1 = pk2(vv.y, vv.y);
            u64 v2 = pk2(vv.z, vv.z), v3 = pk2(vv.w, vv.w);
            #pragma unroll
            for (int ip = 0; ip < 4; ip++) {
                fma2(acc[ip][0], p[ip], v0); fma2(acc[ip][1], p[ip], v1);
                fma2(acc[ip][2], p[ip], v2); fma2(acc[ip][3], p[ip], v3);
            }
        }
    }
    #pragma unroll
    for (int ip = 0; ip < 4; ip++) {
        float lo[4], hi[4];
        #pragma unroll
        for (int f = 0; f < 4; f++) upk2(lo[f], hi[f], acc[ip][f]);
        int i = i0 + ty*8 + 2*ip;
        float4 o0 = {lo[0], lo[1], lo[2], lo[3]};
        float4 o1 = {hi[0], hi[1], hi[2], hi[3]};
        *(float4*)&g_Wh[((size_t)h*NN + i    )*FO + tx*4] = o0;
        *(float4*)&g_Wh[((size_t)h*NN + i + 1)*FO + tx*4] = o1;
    }
}

// ---------------- K3: per-(h,n) s,d + exp factors ----------------
__global__ void k_nodes(const float* __restrict__ a_src,
                        const float* __restrict__ a_dst) {
    int gw = blockIdx.x * (blockDim.x >> 5) + (threadIdx.x >> 5);
    int lane = threadIdx.x & 31;
    int h = gw >> 12, n = gw & (NN - 1);
    const float* wr = g_Wh + ((size_t)h * NN + n) * FO;
    float w0 = wr[lane], w1 = wr[lane + 32];
    float s = w0 * a_src[h*FO + lane] + w1 * a_src[h*FO + lane + 32];
    float d = w0 * a_dst[h*FO + lane] + w1 * a_dst[h*FO + lane + 32];
    #pragma unroll
    for (int off = 16; off; off >>= 1) {
        s += __shfl_xor_sync(0xffffffffu, s, off);
        d += __shfl_xor_sync(0xffffffffu, d, off);
    }
    if (lane == 0) {
        int idx = h * NN + n;
        g_s [idx] = s; g_E1[idx] = __expf(s); g_E2[idx] = __expf(LALPHA * s);
        g_dd[idx] = d; g_F1[idx] = __expf(d); g_F2[idx] = __expf(LALPHA * d);
    }
}

// ---------------- K4: build G tiles in mma B-fragment order (64 feats only) ----------------
__global__ __launch_bounds__(256) void k_gtiles() {
    const int jt = blockIdx.x, h = blockIdx.y;
    const int tid = threadIdx.x, w = tid >> 5, lane = tid & 31;
    const int g = lane >> 2, t = lane & 3;
    uint4* base = g_G + (size_t)(h*NJT + jt) * GT_U4;
    for (int u = w; u < 64; u += 8) {
        int kk = u >> 4, rem = u & 15, nt = rem >> 1, pair = rem & 1;
        int f = nt * 8 + g;
        int j0 = jt * JTT + kk * 16;
        const float* Fv = pair ? g_F2 : g_F1;
        int js[4] = { j0 + 2*t, j0 + 2*t + 1, j0 + 2*t + 8, j0 + 2*t + 9 };
        float v[4];
        #pragma unroll
        for (int m = 0; m < 4; m++)
            v[m] = g_Wh[((size_t)h*NN + js[m])*FO + f] * Fv[h*NN + js[m]];
        unsigned hi[4], lo[4];
        #pragma unroll
        for (int m = 0; m < 4; m++) {
            __nv_bfloat16 hb = __float2bfloat16(v[m]);
            float r = v[m] - __bfloat162float(hb);
            __nv_bfloat16 lb = __float2bfloat16(r);
            hi[m] = __bfloat16_as_ushort(hb);
            lo[m] = __bfloat16_as_ushort(lb);
        }
        uint4 o;
        o.x = hi[0] | (hi[1] << 16);
        o.y = hi[2] | (hi[3] << 16);
        o.z = lo[0] | (lo[1] << 16);
        o.w = lo[2] | (lo[3] << 16);
        base[(size_t)((kk*NTF + nt)*2 + pair)*32 + lane] = o;
    }
}

// ---------------- K5: mma.sync fused attention, scalar Z ----------------
struct SmemMma {
    uint4    G[2][GT_U4];      // 65536 B
    float    dD[2][JTT];       // 512 B
    float    dF1[2][JTT];      // 512 B
    float    dF2[2][JTT];      // 512 B
    unsigned wB[2][2*ROWS];    // 4096 B
};
#define SMEM_MMA sizeof(SmemMma)

__global__ __launch_bounds__(256, 1) void k_attn(float* __restrict__ out) {
    extern __shared__ char smraw[];
    SmemMma* sm = (SmemMma*)smraw;
    const int h  = blockIdx.y;
    const int i0 = blockIdx.x * ROWS;
    const int tid = threadIdx.x, w = tid >> 5, lane = tid & 31;
    const int g = lane >> 2, t = lane & 3;

    const int rA = w*32 + g, rB = rA + 16;
    const float saA = g_s[h*NN + i0 + rA],  sbA = g_s[h*NN + i0 + rA + 8];
    const float saB = g_s[h*NN + i0 + rB],  sbB = g_s[h*NN + i0 + rB + 8];

    float acc1A[NTF][4] = {}, acc2A[NTF][4] = {};
    float acc1B[NTF][4] = {}, acc2B[NTF][4] = {};
    // scalar Z partials: [row][branch]
    float zA1 = 0.f, zA2 = 0.f, zAb1 = 0.f, zAb2 = 0.f;
    float zB1 = 0.f, zB2 = 0.f, zBb1 = 0.f, zBb2 = 0.f;

    auto load_tile = [&](int jt, int b) {
        const uint4* src = g_G + (size_t)(h*NJT + jt) * GT_U4;
        uint32_t dst = smem_u32(&sm->G[b][0]);
        #pragma unroll
        for (int r = 0; r < 8; r++)
            cpa16(dst + (uint32_t)(tid + r*256) * 16, src + tid + r*256);
        if (tid < JTT) {
            cpa4(smem_u32(&sm->dD [b][tid]), &g_dd[h*NN + jt*JTT + tid]);
            cpa4(smem_u32(&sm->dF1[b][tid]), &g_F1[h*NN + jt*JTT + tid]);
            cpa4(smem_u32(&sm->dF2[b][tid]), &g_F2[h*NN + jt*JTT + tid]);
        }
        #pragma unroll
        for (int r = 0; r < 2; r++) {
            int idx = tid + r*256;   // 512 mask words (256 rows x 2)
            cpa4(smem_u32(&sm->wB[b][idx]),
                 &g_bits[(size_t)(i0 + (idx >> 1)) * NW + jt*2 + (idx & 1)]);
        }
    };

    load_tile(0, 0); CP_COMMIT(); CP_WAIT0();
    __syncthreads();

    for (int jt = 0; jt < NJT; jt++) {
        const int b = jt & 1;
        if (jt + 1 < NJT) load_tile(jt + 1, b ^ 1);
        CP_COMMIT();

        const unsigned mA_a0 = sm->wB[b][2*rA],       mA_a1 = sm->wB[b][2*rA + 1];
        const unsigned mA_b0 = sm->wB[b][2*(rA+8)],   mA_b1 = sm->wB[b][2*(rA+8) + 1];
        const unsigned mB_a0 = sm->wB[b][2*rB],       mB_a1 = sm->wB[b][2*rB + 1];
        const unsigned mB_b0 = sm->wB[b][2*(rB+8)],   mB_b1 = sm->wB[b][2*(rB+8) + 1];
        const uint4* Gb = sm->G[b];

        #pragma unroll
        for (int kk = 0; kk < 4; kk++) {
            const int bb = (kk & 1) * 16 + 2*t;
            float2 dlo = *(const float2*)&sm->dD[b][kk*16 + 2*t];
            float2 dhi = *(const float2*)&sm->dD[b][kk*16 + 2*t + 8];
            float2 F1l = *(const float2*)&sm->dF1[b][kk*16 + 2*t];
            float2 F1h = *(const float2*)&sm->dF1[b][kk*16 + 2*t + 8];
            float2 F2l = *(const float2*)&sm->dF2[b][kk*16 + 2*t];
            float2 F2h = *(const float2*)&sm->dF2[b][kk*16 + 2*t + 8];

            uint32_t a1A[4], a2A[4], a1B[4], a2B[4];
            {   // block A, rows rA and rA+8
                const unsigned wa = (kk < 2) ? mA_a0 : mA_a1;
                const unsigned wb = (kk < 2) ? mA_b0 : mA_b1;
                bool e0=(wa>>bb)&1, e1=(wa>>(bb+1))&1, e2=(wa>>(bb+8))&1, e3=(wa>>(bb+9))&1;
                bool q0=(wb>>bb)&1, q1=(wb>>(bb+1))&1, q2=(wb>>(bb+8))&1, q3=(wb>>(bb+9))&1;
                bool c0 = e0 && (saA+dlo.x >= 0.f), c1 = e1 && (saA+dlo.y >= 0.f);
                bool c2 = e2 && (saA+dhi.x >= 0.f), c3 = e3 && (saA+dhi.y >= 0.f);
                bool n0 = e0 && !c0, n1 = e1 && !c1, n2 = e2 && !c2, n3 = e3 && !c3;
                bool u0 = q0 && (sbA+dlo.x >= 0.f), u1 = q1 && (sbA+dlo.y >= 0.f);
                bool u2 = q2 && (sbA+dhi.x >= 0.f), u3 = q3 && (sbA+dhi.y >= 0.f);
                bool v0 = q0 && !u0, v1 = q1 && !u1, v2 = q2 && !u2, v3 = q3 && !u3;
                a1A[0]=(c0?0x3F80u:0u)|(c1?0x3F800000u:0u);
                a2A[0]=(n0?0x3F80u:0u)|(n1?0x3F800000u:0u);
                a1A[1]=(u0?0x3F80u:0u)|(u1?0x3F800000u:0u);
                a2A[1]=(v0?0x3F80u:0u)|(v1?0x3F800000u:0u);
                a1A[2]=(c2?0x3F80u:0u)|(c3?0x3F800000u:0u);
                a2A[2]=(n2?0x3F80u:0u)|(n3?0x3F800000u:0u);
                a1A[3]=(u2?0x3F80u:0u)|(u3?0x3F800000u:0u);
                a2A[3]=(v2?0x3F80u:0u)|(v3?0x3F800000u:0u);
                zA1  += (c0?F1l.x:0.f) + (c1?F1l.y:0.f) + (c2?F1h.x:0.f) + (c3?F1h.y:0.f);
                zA2  += (n0?F2l.x:0.f) + (n1?F2l.y:0.f) + (n2?F2h.x:0.f) + (n3?F2h.y:0.f);
                zAb1 += (u0?F1l.x:0.f) + (u1?F1l.y:0.f) + (u2?F1h.x:0.f) + (u3?F1h.y:0.f);
                zAb2 += (v0?F2l.x:0.f) + (v1?F2l.y:0.f) + (v2?F2h.x:0.f) + (v3?F2h.y:0.f);
            }
            {   // block B, rows rB and rB+8
                const unsigned wa = (kk < 2) ? mB_a0 : mB_a1;
                const unsigned wb = (kk < 2) ? mB_b0 : mB_b1;
                bool e0=(wa>>bb)&1, e1=(wa>>(bb+1))&1, e2=(wa>>(bb+8))&1, e3=(wa>>(bb+9))&1;
                bool q0=(wb>>bb)&1, q1=(wb>>(bb+1))&1, q2=(wb>>(bb+8))&1, q3=(wb>>(bb+9))&1;
                bool c0 = e0 && (saB+dlo.x >= 0.f), c1 = e1 && (saB+dlo.y >= 0.f);
                bool c2 = e2 && (saB+dhi.x >= 0.f), c3 = e3 && (saB+dhi.y >= 0.f);
                bool n0 = e0 && !c0, n1 = e1 && !c1, n2 = e2 && !c2, n3 = e3 && !c3;
                bool u0 = q0 && (sbB+dlo.x >= 0.f), u1 = q1 && (sbB+dlo.y >= 0.f);
                bool u2 = q2 && (sbB+dhi.x >= 0.f), u3 = q3 && (sbB+dhi.y >= 0.f);
                bool v0 = q0 && !u0, v1 = q1 && !u1, v2 = q2 && !u2, v3 = q3 && !u3;
                a1B[0]=(c0?0x3F80u:0u)|(c1?0x3F800000u:0u);
                a2B[0]=(n0?0x3F80u:0u)|(n1?0x3F800000u:0u);
                a1B[1]=(u0?0x3F80u:0u)|(u1?0x3F800000u:0u);
                a2B[1]=(v0?0x3F80u:0u)|(v1?0x3F800000u:0u);
                a1B[2]=(c2?0x3F80u:0u)|(c3?0x3F800000u:0u);
                a2B[2]=(n2?0x3F80u:0u)|(n3?0x3F800000u:0u);
                a1B[3]=(u2?0x3F80u:0u)|(u3?0x3F800000u:0u);
                a2B[3]=(v2?0x3F80u:0u)|(v3?0x3F800000u:0u);
                zB1  += (c0?F1l.x:0.f) + (c1?F1l.y:0.f) + (c2?F1h.x:0.f) + (c3?F1h.y:0.f);
                zB2  += (n0?F2l.x:0.f) + (n1?F2l.y:0.f) + (n2?F2h.x:0.f) + (n3?F2h.y:0.f);
                zBb1 += (u0?F1l.x:0.f) + (u1?F1l.y:0.f) + (u2?F1h.x:0.f) + (u3?F1h.y:0.f);
                zBb2 += (v0?F2l.x:0.f) + (v1?F2l.y:0.f) + (v2?F2h.x:0.f) + (v3?F2h.y:0.f);
            }

            #pragma unroll
            for (int nt = 0; nt < NTF; nt++) {
                uint4 q1v = Gb[((kk*NTF + nt)*2 + 0)*32 + lane];  // G1 hi|lo
                uint4 q2v = Gb[((kk*NTF + nt)*2 + 1)*32 + lane];  // G2 hi|lo
                mma16816(acc1A[nt], a1A, q1v.x, q1v.y);
                mma16816(acc1A[nt], a1A, q1v.z, q1v.w);
                mma16816(acc2A[nt], a2A, q2v.x, q2v.y);
                mma16816(acc2A[nt], a2A, q2v.z, q2v.w);
                mma16816(acc1B[nt], a1B, q1v.x, q1v.y);
                mma16816(acc1B[nt], a1B, q1v.z, q1v.w);
                mma16816(acc2B[nt], a2B, q2v.x, q2v.y);
                mma16816(acc2B[nt], a2B, q2v.z, q2v.w);
            }
        }
        CP_WAIT0();
        __syncthreads();
    }

    // ---- quad-reduce Z partials (lanes 4g..4g+3 cover disjoint j-subsets) ----
    #pragma unroll
    for (int off = 1; off <= 2; off <<= 1) {
        zA1  += __shfl_xor_sync(0xffffffffu, zA1,  off);
        zA2  += __shfl_xor_sync(0xffffffffu, zA2,  off);
        zAb1 += __shfl_xor_sync(0xffffffffu, zAb1, off);
        zAb2 += __shfl_xor_sync(0xffffffffu, zAb2, off);
        zB1  += __shfl_xor_sync(0xffffffffu, zB1,  off);
        zB2  += __shfl_xor_sync(0xffffffffu, zB2,  off);
        zBb1 += __shfl_xor_sync(0xffffffffu, zBb1, off);
        zBb2 += __shfl_xor_sync(0xffffffffu, zBb2, off);
    }

    // ---- epilogue: combine branches, normalize, ELU, store ----
    #pragma unroll
    for (int blk = 0; blk < 2; blk++) {
        float (*A1)[4] = blk ? acc1B : acc1A;
        float (*A2)[4] = blk ? acc2B : acc2A;
        const int ia = i0 + (blk ? rB : rA), ib = ia + 8;
        const float E1a = g_E1[h*NN + ia], E2a = g_E2[h*NN + ia];
        const float E1b = g_E1[h*NN + ib], E2b = g_E2[h*NN + ib];
        const float z1a = blk ? zB1  : zA1,  z2a = blk ? zB2  : zA2;
        const float z1b = blk ? zBb1 : zAb1, z2b = blk ? zBb2 : zAb2;
        const float inva = 1.f / (E1a*z1a + E2a*z2a);
        const float invb = 1.f / (E1b*z1b + E2b*z2b);
        #pragma unroll
        for (int nt = 0; nt < NTF; nt++) {
            float oa0 = (E1a*A1[nt][0] + E2a*A2[nt][0]) * inva;
            float oa1 = (E1a*A1[nt][1] + E2a*A2[nt][1]) * inva;
            float ob0 = (E1b*A1[nt][2] + E2b*A2[nt][2]) * invb;
            float ob1 = (E1b*A1[nt][3] + E2b*A2[nt][3]) * invb;
            oa0 = (oa0 > 0.f) ? oa0 : expm1f(oa0);
            oa1 = (oa1 > 0.f) ? oa1 : expm1f(oa1);
            ob0 = (ob0 > 0.f) ? ob0 : expm1f(ob0);
            ob1 = (ob1 > 0.f) ? ob1 : expm1f(ob1);
            float2 fa = {oa0, oa1}, fb = {ob0, ob1};
            *(float2*)&out[(size_t)ia * (HH*FO) + h*FO + nt*8 + 2*t] = fa;
            *(float2*)&out[(size_t)ib * (HH*FO) + h*FO + nt*8 + 2*t] = fb;
        }
    }
}

// ---------------- launcher ----------------
extern "C" void kernel_launch(void* const* d_in, const int* in_sizes, int n_in,
                              void* d_out, int out_size) {
    const float* X     = (const float*)d_in[0];
    const int*   adj   = (const int*)  d_in[1];
    const float* W     = (const float*)d_in[2];
    const float* a_src = (const float*)d_in[3];
    const float* a_dst = (const float*)d_in[4];
    float* out = (float*)d_out;

    cudaFuncSetAttribute(k_attn, cudaFuncAttributeMaxDynamicSharedMemorySize, SMEM_MMA);

    k_bitpack<<<(NN * NW) / 8, 256>>>(adj);
    k_wh     <<<dim3(NN/128, HH), 256>>>(X, W);
    k_nodes  <<<(HH * NN) / 8, 256>>>(a_src, a_dst);
    k_gtiles <<<dim3(NJT, HH), 256>>>();
    k_attn   <<<dim3(NN/ROWS, HH), 256, SMEM_MMA>>>(out);
}